// round 2
// baseline (speedup 1.0000x reference)
#include <cuda_runtime.h>
#include <math.h>

// Shapes fixed by the problem instance
#define KB    4
#define CIN   8
#define COUT  64
#define NLEN  4096
#define SPLIT 8           // blocks per (k,ci) row in zred
#define TWO_PI_OVER_N 0.0015339807878856412f   // 2*pi/4096

// Scratch
__device__ float g_part_r[KB * CIN][SPLIT];
__device__ float g_part_i[KB * CIN][SPLIT];
__device__ float g_Gr[KB * COUT];
__device__ float g_Gi[KB * COUT];
__device__ float g_cos[NLEN];
__device__ float g_sin[NLEN];

// Kernel 1: 256 reduction blocks (partial DFT bins) + 16 phase-table blocks.
__global__ __launch_bounds__(256) void zred_kernel(
    const float* __restrict__ zr, const float* __restrict__ zi,
    const int* __restrict__ mptr)
{
    const int tid = threadIdx.x;
    const int m   = *mptr;

    if (blockIdx.x >= KB * CIN * SPLIT) {
        // Phase-table block: e^{-i*omega*mu} components, exact arg reduction.
        const int pb = blockIdx.x - KB * CIN * SPLIT;     // 0..15
        const int mu = pb * 256 + tid;
        const int p  = (m * mu) & (NLEN - 1);
        float s, c;
        __sincosf(TWO_PI_OVER_N * (float)p, &s, &c);
        g_cos[mu] = c;
        g_sin[mu] = s;
        return;
    }

    const int b     = blockIdx.x >> 3;      // (k*CIN + ci)
    const int split = blockIdx.x & 7;
    const float* r  = zr + (size_t)b * NLEN + split * 512;
    const float* im = zi + (size_t)b * NLEN + split * 512;

    float ar = 0.f, ai = 0.f;
#pragma unroll
    for (int j = 0; j < 2; j++) {
        const int t = j * 256 + tid;                 // local index within 512
        const int tg = split * 512 + t;              // global t
        const int p = (m * tg) & (NLEN - 1);         // exact phase index
        float s, c;
        __sincosf(TWO_PI_OVER_N * (float)p, &s, &c);
        float x = r[t], y = im[t];
        ar += x * c - y * s;                          // e^{+i*omega*t} * z
        ai += x * s + y * c;
    }

    // warp reduce
#pragma unroll
    for (int off = 16; off > 0; off >>= 1) {
        ar += __shfl_down_sync(0xffffffff, ar, off);
        ai += __shfl_down_sync(0xffffffff, ai, off);
    }
    __shared__ float swr[8], swi[8];
    if ((tid & 31) == 0) { swr[tid >> 5] = ar; swi[tid >> 5] = ai; }
    __syncthreads();
    if (tid == 0) {
        float tr = 0.f, ti = 0.f;
#pragma unroll
        for (int w = 0; w < 8; w++) { tr += swr[w]; ti += swi[w]; }
        g_part_r[b][split] = tr;
        g_part_i[b][split] = ti;
    }
}

// Kernel 2: one tiny block. Each thread owns one (k,co): sum partials into
// Z[k,ci], apply weights, compute scalar gate, store gated G.
__global__ __launch_bounds__(256) void prep_kernel(
    const float* __restrict__ A, const float* __restrict__ beta,
    const float* __restrict__ bias)
{
    const int tid = threadIdx.x;            // b = k*COUT + co
    const int k   = tid >> 6;
    const int co  = tid & 63;

    float Gr = 0.f, Gi = 0.f;
#pragma unroll
    for (int ci = 0; ci < CIN; ci++) {
        float Zr = 0.f, Zi = 0.f;
#pragma unroll
        for (int s = 0; s < SPLIT; s++) {
            Zr += g_part_r[k * CIN + ci][s];
            Zi += g_part_i[k * CIN + ci][s];
        }
        float a = fabsf(A[co * CIN + ci]);
        float sb, cb;
        __sincosf(beta[co * CIN + ci], &sb, &cb);   // beta in [-pi,pi]
        float Wr = a * cb, Wi = a * sb;
        Gr += Wr * Zr - Wi * Zi;
        Gi += Wr * Zi + Wi * Zr;
    }
    float mag  = sqrtf(Gr * Gr + Gi * Gi);
    float gate = (1.f / (1.f + __expf(-(mag + bias[co])))) / (mag + 1e-5f);
    g_Gr[tid] = gate * Gr;
    g_Gi[tid] = gate * Gi;
}

// Kernel 3: pure stream. out_r[b][mu] = Gr*c[mu] + Gi*s[mu];
//                        out_i[b][mu] = Gi*c[mu] - Gr*s[mu].
__global__ __launch_bounds__(256) void out_kernel(float* __restrict__ out)
{
    const int b  = blockIdx.x;              // k*COUT + co
    const float gr = g_Gr[b];
    const float gi = g_Gi[b];

    float* outr = out + (size_t)b * NLEN;
    float* outi = out + (size_t)KB * COUT * NLEN + (size_t)b * NLEN;

    const int mu0 = blockIdx.y * 1024 + threadIdx.x * 4;
    const float4 c4 = *reinterpret_cast<const float4*>(&g_cos[mu0]);
    const float4 s4 = *reinterpret_cast<const float4*>(&g_sin[mu0]);

    float4 vr, vi;
    vr.x = gr * c4.x + gi * s4.x;  vi.x = gi * c4.x - gr * s4.x;
    vr.y = gr * c4.y + gi * s4.y;  vi.y = gi * c4.y - gr * s4.y;
    vr.z = gr * c4.z + gi * s4.z;  vi.z = gi * c4.z - gr * s4.z;
    vr.w = gr * c4.w + gi * s4.w;  vi.w = gi * c4.w - gr * s4.w;

    *reinterpret_cast<float4*>(outr + mu0) = vr;
    *reinterpret_cast<float4*>(outi + mu0) = vi;
}

extern "C" void kernel_launch(void* const* d_in, const int* in_sizes, int n_in,
                              void* d_out, int out_size)
{
    const float* z_real = (const float*)d_in[0];
    const float* z_imag = (const float*)d_in[1];
    const float* A      = (const float*)d_in[2];
    const float* beta   = (const float*)d_in[3];
    const float* bias   = (const float*)d_in[4];
    const int*   mptr   = (const int*)d_in[5];
    float* out = (float*)d_out;

    zred_kernel<<<KB * CIN * SPLIT + 16, 256>>>(z_real, z_imag, mptr);
    prep_kernel<<<1, 256>>>(A, beta, bias);
    dim3 grid(KB * COUT, NLEN / 1024);
    out_kernel<<<grid, 256>>>(out);
}

// round 4
// speedup vs baseline: 1.7910x; 1.7910x over previous
#include <cuda_runtime.h>
#include <math.h>

// Shapes fixed by the problem instance
#define KB    4
#define CIN   8
#define COUT  64
#define NLEN  4096
#define SPLIT 16          // blocks per (k,ci) row in zred
#define TWO_PI_OVER_N 0.0015339807878856412f   // 2*pi/4096

// Scratch
__device__ float g_part_r[KB * CIN][SPLIT];
__device__ float g_part_i[KB * CIN][SPLIT];
__device__ float g_cos[NLEN];
__device__ float g_sin[NLEN];

// Kernel 1: 512 partial-DFT blocks (one element per thread) + 16 phase-table
// blocks, all in one launch.
__global__ __launch_bounds__(256) void zred_kernel(
    const float* __restrict__ zr, const float* __restrict__ zi,
    const int* __restrict__ mptr)
{
    const int tid = threadIdx.x;
    const int m   = *mptr;

    if (blockIdx.x >= KB * CIN * SPLIT) {
        // Phase table: components of e^{i*omega*mu}, exact arg reduction.
        const int mu = (blockIdx.x - KB * CIN * SPLIT) * 256 + tid;
        const int p  = (m * mu) & (NLEN - 1);
        float s, c;
        __sincosf(TWO_PI_OVER_N * (float)p, &s, &c);
        g_cos[mu] = c;
        g_sin[mu] = s;
        return;
    }

    const int b     = blockIdx.x >> 4;      // (k*CIN + ci)
    const int split = blockIdx.x & 15;
    const int tg    = split * 256 + tid;    // global sample index

    const int p = (m * tg) & (NLEN - 1);    // exact phase index
    float s, c;
    __sincosf(TWO_PI_OVER_N * (float)p, &s, &c);
    const float x = zr[(size_t)b * NLEN + tg];
    const float y = zi[(size_t)b * NLEN + tg];
    float ar = x * c - y * s;               // e^{+i*omega*t} * z
    float ai = x * s + y * c;

    // warp reduce
#pragma unroll
    for (int off = 16; off > 0; off >>= 1) {
        ar += __shfl_down_sync(0xffffffff, ar, off);
        ai += __shfl_down_sync(0xffffffff, ai, off);
    }
    __shared__ float swr[8], swi[8];
    if ((tid & 31) == 0) { swr[tid >> 5] = ar; swi[tid >> 5] = ai; }
    __syncthreads();
    if (tid == 0) {
        float tr = 0.f, ti = 0.f;
#pragma unroll
        for (int w = 0; w < 8; w++) { tr += swr[w]; ti += swi[w]; }
        g_part_r[b][split] = tr;
        g_part_i[b][split] = ti;
    }
}

// Kernel 2: one block per (k,co). Warp-redundant prologue builds
// G = sum_ci |A| e^{i beta} Z[k,ci] and the scalar gate (no smem, no sync),
// then streams out[mu] = gate * e^{-i omega mu} * G via the phase table.
__global__ __launch_bounds__(256) void out_kernel(
    const float* __restrict__ A, const float* __restrict__ beta,
    const float* __restrict__ bias, float* __restrict__ out)
{
    const int b    = blockIdx.x;            // k*COUT + co
    const int k    = b >> 6;
    const int co   = b & 63;
    const int tid  = threadIdx.x;
    const int lane = tid & 31;
    const int ci   = lane & 7;              // 4x redundant within each warp

    // Per-lane: Z[k,ci] from the 16 partials, times the complex weight.
    float Zr = 0.f, Zi = 0.f;
#pragma unroll
    for (int s = 0; s < SPLIT; s++) {
        Zr += g_part_r[k * CIN + ci][s];
        Zi += g_part_i[k * CIN + ci][s];
    }
    const float a = fabsf(A[co * CIN + ci]);
    float sb, cb;
    __sincosf(beta[co * CIN + ci], &sb, &cb);
    const float Wr = a * cb, Wi = a * sb;
    float Gr = Wr * Zr - Wi * Zi;
    float Gi = Wr * Zi + Wi * Zr;

    // Fold the 8 ci-lanes of each group: every lane ends with the full sum.
#pragma unroll
    for (int off = 1; off < 8; off <<= 1) {
        Gr += __shfl_xor_sync(0xffffffff, Gr, off);
        Gi += __shfl_xor_sync(0xffffffff, Gi, off);
    }

    const float mag  = sqrtf(Gr * Gr + Gi * Gi);
    const float gate = (1.f / (1.f + __expf(-(mag + bias[co])))) / (mag + 1e-5f);
    const float gr = gate * Gr, gi = gate * Gi;

    float* outr = out + (size_t)b * NLEN;
    float* outi = out + (size_t)KB * COUT * NLEN + (size_t)b * NLEN;

    // Stream all 4096 mu: 4 float4-pairs per thread.
#pragma unroll
    for (int j = 0; j < 4; j++) {
        const int mu0 = j * 1024 + tid * 4;
        const float4 c4 = *reinterpret_cast<const float4*>(&g_cos[mu0]);
        const float4 s4 = *reinterpret_cast<const float4*>(&g_sin[mu0]);

        float4 vr, vi;
        vr.x = gr * c4.x + gi * s4.x;  vi.x = gi * c4.x - gr * s4.x;
        vr.y = gr * c4.y + gi * s4.y;  vi.y = gi * c4.y - gr * s4.y;
        vr.z = gr * c4.z + gi * s4.z;  vi.z = gi * c4.z - gr * s4.z;
        vr.w = gr * c4.w + gi * s4.w;  vi.w = gi * c4.w - gr * s4.w;

        *reinterpret_cast<float4*>(outr + mu0) = vr;
        *reinterpret_cast<float4*>(outi + mu0) = vi;
    }
}

extern "C" void kernel_launch(void* const* d_in, const int* in_sizes, int n_in,
                              void* d_out, int out_size)
{
    const float* z_real = (const float*)d_in[0];
    const float* z_imag = (const float*)d_in[1];
    const float* A      = (const float*)d_in[2];
    const float* beta   = (const float*)d_in[3];
    const float* bias   = (const float*)d_in[4];
    const int*   mptr   = (const int*)d_in[5];
    float* out = (float*)d_out;

    zred_kernel<<<KB * CIN * SPLIT + 16, 256>>>(z_real, z_imag, mptr);
    out_kernel<<<KB * COUT, 256>>>(A, beta, bias, out);
}